// round 4
// baseline (speedup 1.0000x reference)
#include <cuda_runtime.h>
#include <math.h>

#define NQ 24
#define BATCH 4
#define DIMQ (1 << NQ)          // 2^24 rows
#define HALF (1 << (NQ - 1))    // 2^23 pair count
#define TPB 256

// One thread per pair index i in [0, 2^23).
// State (DIM, B=4) row-major -> each row is one float4 (all 4 batches).
// Pair partner row: i + 2^23 (qubit 0 = most significant axis).
// Output: (2, DIM, B): real plane then imag plane.
// R1 shape (best occupancy: 42 regs, TPB 256) + streaming cache hints.
__global__ __launch_bounds__(TPB) void u_gate_kernel(
    const float4* __restrict__ sr,
    const float4* __restrict__ si,
    const float*  __restrict__ thetas,  // (3,4): phi[4], theta[4], omega[4]
    float4* __restrict__ outr,
    float4* __restrict__ outi)
{
    // u[b][0..7] = {u00r,u00i, u01r,u01i, u10r,u10i, u11r,u11i}
    __shared__ float u[BATCH * 8];

    const int tid = threadIdx.x;
    if (tid < BATCH) {
        float phi   = thetas[0 * BATCH + tid];
        float theta = thetas[1 * BATCH + tid];
        float omega = thetas[2 * BATCH + tid];
        float a = 0.5f * (phi + omega);
        float b = 0.5f * (phi - omega);
        float sa, ca, sb, cb, st, ct;
        sincosf(a, &sa, &ca);
        sincosf(b, &sb, &cb);
        sincosf(0.5f * theta, &st, &ct);
        // u00 = ct*(ca - i sa); u01 = -st*(cb + i sb)
        // u10 = st*(cb - i sb); u11 = ct*(ca + i sa)
        float* ub = &u[tid * 8];
        ub[0] =  ct * ca;  ub[1] = -ct * sa;
        ub[2] = -st * cb;  ub[3] = -st * sb;
        ub[4] =  st * cb;  ub[5] = -st * sb;
        ub[6] =  ct * ca;  ub[7] =  ct * sa;
    }
    __syncthreads();

    const unsigned i0 = blockIdx.x * TPB + tid;  // pair index, < 2^23
    const unsigned i1 = i0 + HALF;

    // 4 independent 16B streaming loads (evict-first in L2)
    float4 s0r = __ldcs(&sr[i0]);
    float4 s0i = __ldcs(&si[i0]);
    float4 s1r = __ldcs(&sr[i1]);
    float4 s1i = __ldcs(&si[i1]);

    float4 o0r, o0i, o1r, o1i;

    const float* s0rf = (const float*)&s0r;
    const float* s0if = (const float*)&s0i;
    const float* s1rf = (const float*)&s1r;
    const float* s1if = (const float*)&s1i;
    float* o0rf = (float*)&o0r;
    float* o0if = (float*)&o0i;
    float* o1rf = (float*)&o1r;
    float* o1if = (float*)&o1i;

#pragma unroll
    for (int b = 0; b < BATCH; b++) {
        float u00r = u[b*8+0], u00i = u[b*8+1];
        float u01r = u[b*8+2], u01i = u[b*8+3];
        float u10r = u[b*8+4], u10i = u[b*8+5];
        float u11r = u[b*8+6], u11i = u[b*8+7];
        float x0r = s0rf[b], x0i = s0if[b];
        float x1r = s1rf[b], x1i = s1if[b];

        o0rf[b] = u00r*x0r - u00i*x0i + u01r*x1r - u01i*x1i;
        o0if[b] = u00r*x0i + u00i*x0r + u01r*x1i + u01i*x1r;
        o1rf[b] = u10r*x0r - u10i*x0i + u11r*x1r - u11i*x1i;
        o1if[b] = u10r*x0i + u10i*x0r + u11r*x1i + u11i*x1r;
    }

    __stcs(&outr[i0], o0r);
    __stcs(&outi[i0], o0i);
    __stcs(&outr[i1], o1r);
    __stcs(&outi[i1], o1i);
}

extern "C" void kernel_launch(void* const* d_in, const int* in_sizes, int n_in,
                              void* d_out, int out_size)
{
    const float4* sr = (const float4*)d_in[0];   // state_real (DIM, 4)
    const float4* si = (const float4*)d_in[1];   // state_imag (DIM, 4)
    const float*  th = (const float*)d_in[2];    // thetas (3, 4)

    float4* outr = (float4*)d_out;               // real plane
    float4* outi = outr + DIMQ;                  // imag plane

    dim3 grid(HALF / TPB);  // 32768 blocks of 256
    u_gate_kernel<<<grid, TPB>>>(sr, si, th, outr, outi);
}